// round 9
// baseline (speedup 1.0000x reference)
#include <cuda_runtime.h>
#include <cuda_fp16.h>
#include <cstdint>

// Problem constants (fixed for MoEDense_10411000726246)
#define TB 8192     // batch
#define DD 128      // input dim (K)
#define FF 128      // output dim (N)
#define TT 64       // num experts
#define TM 32       // rows per GEMM tile
#define NCTA 296    // persistent CTAs (2 per SM, all co-resident)
#define NSORT 64    // sort CTAs (128 rows each)
#define MAXT 2      // max tiles per CTA (320 <= 2*296)

#define MAX_TILES (TB / TM + TT)        // 320
#define PAD_CAP   (TB + TT * TM)        // 10240

// Scratch (no allocations allowed)
__device__ int g_partial[NSORT * TT];
__device__ int g_bar1 = 0, g_bar2 = 0, g_dep = 0;
__device__ int g_rowOrder[PAD_CAP];
__device__ __half g_Wh[TT * DD * FF];   // fp16(W)

// ---------------------------------------------------------------------------
__device__ __forceinline__ uint32_t smem_u32(const void* p) {
    uint32_t a;
    asm("{ .reg .u64 t; cvta.to.shared.u64 t, %1; cvt.u32.u64 %0, t; }"
        : "=r"(a) : "l"(p));
    return a;
}

#define CP_ASYNC16(dst, src)                                                  \
    asm volatile("cp.async.cg.shared.global [%0], [%1], 16;"                  \
                 :: "r"(dst), "l"(src) : "memory")
#define CP_COMMIT_WAIT()                                                      \
    asm volatile("cp.async.commit_group;\n\tcp.async.wait_group 0;"           \
                 ::: "memory")

#define LDSM_X4(r0, r1, r2, r3, addr)                                         \
    asm volatile("ldmatrix.sync.aligned.m8n8.x4.shared.b16 "                  \
                 "{%0,%1,%2,%3}, [%4];"                                       \
                 : "=r"(r0), "=r"(r1), "=r"(r2), "=r"(r3) : "r"(addr))

#define LDSM_X4_T(r0, r1, r2, r3, addr)                                       \
    asm volatile("ldmatrix.sync.aligned.m8n8.x4.trans.shared.b16 "            \
                 "{%0,%1,%2,%3}, [%4];"                                       \
                 : "=r"(r0), "=r"(r1), "=r"(r2), "=r"(r3) : "r"(addr))

#define MMA_16816_F16(d, a0, a1, a2, a3, b0, b1)                              \
    asm volatile("mma.sync.aligned.m16n8k16.row.col.f32.f16.f16.f32 "         \
                 "{%0,%1,%2,%3}, {%4,%5,%6,%7}, {%8,%9}, {%0,%1,%2,%3};"      \
                 : "+f"((d)[0]), "+f"((d)[1]), "+f"((d)[2]), "+f"((d)[3])     \
                 : "r"(a0), "r"(a1), "r"(a2), "r"(a3), "r"(b0), "r"(b1))

// smem layout (GEMM phase); sort scratch aliases the front of SM_A.
#define APAD 136
#define AROWB (APAD * 2)                 // 272 bytes (128 fp16 + 16B pad)
#define SM_A   0
#define SM_B   (SM_A + TM * AROWB)       // 8704
#define SM_BIAS (SM_B + DD * AROWB)      // 43520
#define SM_ROWS (SM_BIAS + FF * 4)       // 44032
#define SM_TOTAL (SM_ROWS + TM * 4)      // 44160

__device__ __forceinline__ void grid_barrier(int* ctr, int tid) {
    __threadfence();
    __syncthreads();
    if (tid == 0) {
        atomicAdd(ctr, 1);
        volatile int* v = (volatile int*)ctr;
        while (*v < NCTA) { }
    }
    __syncthreads();
    __threadfence();
}

// ---------------------------------------------------------------------------
// Single fused kernel: sort + W convert + grouped fp16 HMMA GEMM.
// 296 CTAs x 256 threads, all co-resident (2 per SM).
// ---------------------------------------------------------------------------
__global__ __launch_bounds__(256, 2)
void k_all(const int* __restrict__ tidx, const float* __restrict__ X,
           const float* __restrict__ W, const float* __restrict__ Bias,
           float* __restrict__ Y) {
    extern __shared__ char smem[];
    const uint32_t sbase = smem_u32(smem);
    int tid = threadIdx.x;
    int bid = blockIdx.x;
    int wid = tid >> 5;
    int lid = tid & 31;

    // Phase A/B scratch (aliases SM_A region; dead before GEMM phase)
    int* s_bins  = (int*)(smem);           // [64]
    int* s_total = (int*)(smem + 256);     // [64]
    int* s_myb   = (int*)(smem + 512);     // [64]
    int* s_roffv = (int*)(smem + 768);     // [64]
    int* s_toffv = (int*)(smem + 1024);    // [65]

    // ================= Phase A: histogram (64 CTAs) + W convert (232) =====
    int my_e = -1, my_loc = 0, my_row = -1;
    if (bid < NSORT) {
        if (tid < TT) s_bins[tid] = 0;
        __syncthreads();
        if (tid < 128) {
            my_row = bid * 128 + tid;
            my_e = tidx[my_row];
            my_e = min(max(my_e, 0), TT - 1);
            my_loc = atomicAdd(&s_bins[my_e], 1);
        }
        __syncthreads();
        if (tid < TT) g_partial[bid * TT + tid] = s_bins[tid];
    } else {
        // W fp32 -> fp16 convert, grid-stride over 232 CTAs
        int cb = bid - NSORT;
        const int WF4 = TT * DD * FF / 4;   // 262144
        for (int i = cb * 256 + tid; i < WF4; i += (NCTA - NSORT) * 256) {
            float4 v = ((const float4*)W)[i];
            __half2 h01 = __float22half2_rn(make_float2(v.x, v.y));
            __half2 h23 = __float22half2_rn(make_float2(v.z, v.w));
            uint2 hv = make_uint2(*(uint32_t*)&h01, *(uint32_t*)&h23);
            *(uint2*)(g_Wh + (size_t)i * 4) = hv;
        }
    }

    grid_barrier(&g_bar1, tid);

    // ================= Phase B: scan + scatter + tile plan =================
    if (tid < TT) {
        int tot = 0, myb = 0;
        #pragma unroll 4
        for (int i = 0; i < NSORT; i++) {
            int p = g_partial[i * TT + tid];
            if (i < bid) myb += p;
            tot += p;
        }
        s_total[tid] = tot;
        s_myb[tid]   = myb;
    }
    __syncthreads();

    if (tid == 0) {
        int roff = 0, toff = 0;
        #pragma unroll
        for (int e2 = 0; e2 < TT; e2++) {
            s_roffv[e2] = roff;
            s_toffv[e2] = toff;
            int nt = (s_total[e2] + TM - 1) / TM;
            roff += nt * TM;
            toff += nt;
        }
        s_toffv[TT] = toff;
    }
    __syncthreads();

    if (my_row >= 0)
        g_rowOrder[s_roffv[my_e] + s_myb[my_e] + my_loc] = my_row;

    // Stash this CTA's tile metadata in registers (smem dies at barrier 2)
    int ntiles = s_toffv[TT];
    int te[MAXT], tbm[MAXT], trn[MAXT];
    int ntm = 0;
    #pragma unroll
    for (int j = 0; j < MAXT; j++) {
        int t = bid + j * NCTA;
        if (t < ntiles) {
            int e2 = 0;
            while (s_toffv[e2 + 1] <= t) e2++;
            int j2 = t - s_toffv[e2];
            te[j]  = e2;
            tbm[j] = s_roffv[e2] + j2 * TM;
            trn[j] = min(TM, s_total[e2] - j2 * TM);
            ntm = j + 1;
        }
    }

    grid_barrier(&g_bar2, tid);

    // ================= Phase C: tile loop (<= 2 tiles per CTA) =============
    int warpM = wid >> 2;     // 0..1
    int warpN = wid & 3;      // 0..3

    int* rows_s   = (int*)(smem + SM_ROWS);
    float* bias_s = (float*)(smem + SM_BIAS);

    for (int j = 0; j < ntm; j++) {
        int e     = te[j];
        int base  = tbm[j];
        int nrows = trn[j];

        if (tid < TM) rows_s[tid] = (tid < nrows) ? g_rowOrder[base + tid] : -1;
        if (tid >= 128) bias_s[tid - 128] = Bias[e * FF + (tid - 128)];

        // B: cp.async fp16 W (32KB), 128 k-rows x 16 chunks of 16B
        {
            const char* WB = (const char*)(g_Wh + (size_t)e * DD * FF);
            #pragma unroll
            for (int it = 0; it < 8; it++) {
                int idx = tid + it * 256;
                int k = idx >> 4, c = idx & 15;
                CP_ASYNC16(sbase + SM_B + (uint32_t)(k * AROWB + c * 16),
                           WB + (uint32_t)(k * 256 + c * 16));
            }
        }
        __syncthreads();   // rows_s visible

        // A: on-the-fly fp32 -> fp16 convert (32 rows x 32 float4)
        #pragma unroll
        for (int it = 0; it < 4; it++) {
            int idx = tid + it * 256;          // 1024
            int m  = idx >> 5;
            int c4 = idx & 31;
            int r = rows_s[m];
            float4 v = (r >= 0) ? *(const float4*)&X[(size_t)r * DD + c4 * 4]
                                : make_float4(0.f, 0.f, 0.f, 0.f);
            __half2 h01 = __float22half2_rn(make_float2(v.x, v.y));
            __half2 h23 = __float22half2_rn(make_float2(v.z, v.w));
            uint2 hv = make_uint2(*(uint32_t*)&h01, *(uint32_t*)&h23);
            *(uint2*)(smem + SM_A + (uint32_t)(m * AROWB + c4 * 8)) = hv;
        }
        CP_COMMIT_WAIT();
        __syncthreads();

        // Mainloop: 8 warps = 2(M) x 4(N); warp tile 16x32
        float acc[4][4];
        #pragma unroll
        for (int nn = 0; nn < 4; nn++)
            #pragma unroll
            for (int q = 0; q < 4; q++) acc[nn][q] = 0.f;

        uint32_t aLane = sbase + SM_A
                       + (uint32_t)((warpM * 16 + (lid & 15)) * AROWB
                       + (lid >> 4) * 16);
        uint32_t bLane = sbase + SM_B
                       + (uint32_t)((lid & 15) * AROWB
                       + (warpN * 32 + (lid >> 4) * 8) * 2);

        #pragma unroll
        for (int k0 = 0; k0 < DD; k0 += 16) {
            uint32_t a0, a1, a2, a3;
            LDSM_X4(a0, a1, a2, a3, aLane + k0 * 2);
            uint32_t bfr[2][4];
            #pragma unroll
            for (int jn = 0; jn < 2; jn++)
                LDSM_X4_T(bfr[jn][0], bfr[jn][1], bfr[jn][2], bfr[jn][3],
                          bLane + k0 * AROWB + jn * 32);
            #pragma unroll
            for (int jn = 0; jn < 2; jn++) {
                MMA_16816_F16(acc[jn * 2],     a0, a1, a2, a3,
                              bfr[jn][0], bfr[jn][1]);
                MMA_16816_F16(acc[jn * 2 + 1], a0, a1, a2, a3,
                              bfr[jn][2], bfr[jn][3]);
            }
        }

        // Epilogue: c-frag -> gmem with bias
        int m0 = warpM * 16 + (lid >> 2);
        int m1 = m0 + 8;
        int gr0 = rows_s[m0];
        int gr1 = rows_s[m1];
        int colBase = warpN * 32 + (lid & 3) * 2;
        #pragma unroll
        for (int nn = 0; nn < 4; nn++) {
            int col = colBase + nn * 8;
            float bx = bias_s[col], by = bias_s[col + 1];
            if (gr0 >= 0) {
                float2 o = make_float2(acc[nn][0] + bx, acc[nn][1] + by);
                *(float2*)&Y[(size_t)gr0 * FF + col] = o;
            }
            if (gr1 >= 0) {
                float2 o = make_float2(acc[nn][2] + bx, acc[nn][3] + by);
                *(float2*)&Y[(size_t)gr1 * FF + col] = o;
            }
        }

        __syncthreads();   // smem reuse safe for next tile
    }

    // Reset barrier counters for next graph replay
    if (tid == 0) {
        int d = atomicAdd(&g_dep, 1);
        if (d == NCTA - 1) {
            g_bar1 = 0; g_bar2 = 0; g_dep = 0;
            __threadfence();
        }
    }
}

// ---------------------------------------------------------------------------
extern "C" void kernel_launch(void* const* d_in, const int* in_sizes, int n_in,
                              void* d_out, int out_size) {
    const float* X    = (const float*)d_in[0];   // [B, D] fp32
    const int*   tidx = (const int*)d_in[1];     // [B] int32
    const float* W    = (const float*)d_in[2];   // [T, D, F] fp32
    const float* Bias = (const float*)d_in[3];   // [T, F] fp32
    float* Y = (float*)d_out;                    // [B, F] fp32

    (void)in_sizes; (void)n_in; (void)out_size;

    cudaFuncSetAttribute(k_all, cudaFuncAttributeMaxDynamicSharedMemorySize,
                         SM_TOTAL);

    k_all<<<NCTA, 256, SM_TOTAL>>>(tidx, X, W, Bias, Y);
}

// round 10
// speedup vs baseline: 1.2937x; 1.2937x over previous
#include <cuda_runtime.h>
#include <cuda_fp16.h>
#include <cstdint>

// Problem constants (fixed for MoEDense_10411000726246)
#define TB 8192     // batch
#define DD 128      // input dim (K)
#define FF 128      // output dim (N)
#define TT 64       // num experts
#define TM 32       // rows per GEMM tile
#define NBLK 32     // sort blocks (grid-barrier participants)
#define CONVBLK 116 // W-convert blocks (NBLK+CONVBLK = 148 = one wave)

#define MAX_TILES (TB / TM + TT)        // 320
#define PAD_CAP   (TB + TT * TM)        // 10240

// Scratch (no allocations allowed)
__device__ int g_partial[NBLK * TT];
__device__ int g_arrive = 0;
__device__ int g_depart = 0;
__device__ int g_tileExpert[MAX_TILES];
__device__ int g_tileBase[MAX_TILES];
__device__ int g_tileRows[MAX_TILES];
__device__ int g_rowOrder[PAD_CAP];
__device__ __half g_Wh[TT * DD * FF];   // fp16(W)

// ---------------------------------------------------------------------------
__device__ __forceinline__ uint32_t smem_u32(const void* p) {
    uint32_t a;
    asm("{ .reg .u64 t; cvta.to.shared.u64 t, %1; cvt.u32.u64 %0, t; }"
        : "=r"(a) : "l"(p));
    return a;
}

#define CP_ASYNC16(dst, src)                                                  \
    asm volatile("cp.async.cg.shared.global [%0], [%1], 16;"                  \
                 :: "r"(dst), "l"(src) : "memory")
#define CP_COMMIT_WAIT()                                                      \
    asm volatile("cp.async.commit_group;\n\tcp.async.wait_group 0;"           \
                 ::: "memory")

#define LDSM_X4(r0, r1, r2, r3, addr)                                         \
    asm volatile("ldmatrix.sync.aligned.m8n8.x4.shared.b16 "                  \
                 "{%0,%1,%2,%3}, [%4];"                                       \
                 : "=r"(r0), "=r"(r1), "=r"(r2), "=r"(r3) : "r"(addr))

#define LDSM_X4_T(r0, r1, r2, r3, addr)                                       \
    asm volatile("ldmatrix.sync.aligned.m8n8.x4.trans.shared.b16 "            \
                 "{%0,%1,%2,%3}, [%4];"                                       \
                 : "=r"(r0), "=r"(r1), "=r"(r2), "=r"(r3) : "r"(addr))

#define MMA_16816_F16(d, a0, a1, a2, a3, b0, b1)                              \
    asm volatile("mma.sync.aligned.m16n8k16.row.col.f32.f16.f16.f32 "         \
                 "{%0,%1,%2,%3}, {%4,%5,%6,%7}, {%8,%9}, {%0,%1,%2,%3};"      \
                 : "+f"((d)[0]), "+f"((d)[1]), "+f"((d)[2]), "+f"((d)[3])     \
                 : "r"(a0), "r"(a1), "r"(a2), "r"(a3), "r"(b0), "r"(b1))

// ---------------------------------------------------------------------------
// K_prep: blocks [0,32) = fused histogram/scan/plan/scatter (grid barrier
// among themselves); blocks [32,148) = fp32 -> fp16 convert of W only.
// ---------------------------------------------------------------------------
__global__ __launch_bounds__(256) void k_prep(const int* __restrict__ tidx,
                                              const float* __restrict__ W) {
    int t = threadIdx.x;
    int b = blockIdx.x;

    if (b >= NBLK) {
        // ---- W convert path ----
        int cb = b - NBLK;
        const int WF4 = TT * DD * FF / 4;   // 262144
        for (int i = cb * 256 + t; i < WF4; i += CONVBLK * 256) {
            float4 v = ((const float4*)W)[i];
            __half2 h01 = __float22half2_rn(make_float2(v.x, v.y));
            __half2 h23 = __float22half2_rn(make_float2(v.z, v.w));
            uint2 hv = make_uint2(*(uint32_t*)&h01, *(uint32_t*)&h23);
            *(uint2*)(g_Wh + (size_t)i * 4) = hv;
        }
        return;
    }

    // ---- sort path (blocks 0..31) ----
    __shared__ int s_bins[TT];
    __shared__ int s_total[TT];
    __shared__ int s_base[TT];
    __shared__ int s_roff[TT];
    __shared__ int s_toff[TT];
    __shared__ int s_ntiles;

    if (t < TT) s_bins[t] = 0;
    __syncthreads();

    int row = b * 256 + t;
    int e = tidx[row];
    e = min(max(e, 0), TT - 1);
    int loc = atomicAdd(&s_bins[e], 1);
    __syncthreads();

    if (t < TT) g_partial[b * TT + t] = s_bins[t];
    __threadfence();
    __syncthreads();

    if (t == 0) {
        atomicAdd(&g_arrive, 1);
        volatile int* v = (volatile int*)&g_arrive;
        while (*v < NBLK) { }
    }
    __syncthreads();
    __threadfence();

    if (t < TT) {
        int tot = 0, mybase = 0;
        #pragma unroll 4
        for (int i = 0; i < NBLK; i++) {
            int p = g_partial[i * TT + t];
            if (i < b) mybase += p;
            tot += p;
        }
        s_total[t] = tot;
        s_base[t] = mybase;
    }
    __syncthreads();

    if (t == 0) {
        int roff = 0, toff = 0;
        #pragma unroll
        for (int i = 0; i < TT; i++) {
            s_roff[i] = roff;
            s_toff[i] = toff;
            int nt = (s_total[i] + TM - 1) / TM;
            roff += nt * TM;
            toff += nt;
        }
        s_ntiles = toff;
    }
    __syncthreads();

    if (t < TT) s_base[t] += s_roff[t];
    __syncthreads();

    g_rowOrder[s_base[e] + loc] = row;

    if (b == 0) {
        if (t < TT) {
            int tot = s_total[t];
            int nt = (tot + TM - 1) / TM;
            int tb = s_toff[t];
            int rb = s_roff[t];
            for (int j = 0; j < nt; j++) {
                g_tileExpert[tb + j] = t;
                g_tileBase[tb + j]   = rb + j * TM;
                g_tileRows[tb + j]   = min(TM, tot - j * TM);
            }
        }
        __syncthreads();
        for (int idx = s_ntiles + t; idx < MAX_TILES; idx += 256)
            g_tileExpert[idx] = -1;
    }

    if (t == 0) {
        int d = atomicAdd(&g_depart, 1);
        if (d == NBLK - 1) { g_arrive = 0; g_depart = 0; __threadfence(); }
    }
}

// ---------------------------------------------------------------------------
// K_gemm: 32x128 tile per CTA, single fp16 pass K=128.
//   256 threads = 8 warps (2M x 4N); warp tile 16x32. fp32 accumulation.
//   A converted fp32->fp16 on the fly (X read once per row, no pre-convert).
// ---------------------------------------------------------------------------
#define APAD 136
#define AROWB (APAD * 2)                 // 272 bytes (128 fp16 + 16B pad)
#define SM_A   0
#define SM_B   (SM_A + TM * AROWB)       // 8704
#define SM_BIAS (SM_B + DD * AROWB)      // 43520
#define SM_ROWS (SM_BIAS + FF * 4)       // 44032
#define SM_TOTAL (SM_ROWS + TM * 4)      // 44160

__global__ __launch_bounds__(256, 3)
void k_gemm(const float* __restrict__ X, const float* __restrict__ Bias,
            float* __restrict__ Y) {
    extern __shared__ char smem[];
    const uint32_t sbase = smem_u32(smem);

    int tile = blockIdx.x;
    int e = g_tileExpert[tile];
    if (e < 0) return;
    int base  = g_tileBase[tile];
    int nrows = g_tileRows[tile];
    int tid = threadIdx.x;
    int wid = tid >> 5;
    int lid = tid & 31;

    int* rows_s   = (int*)(smem + SM_ROWS);
    float* bias_s = (float*)(smem + SM_BIAS);

    // Stage rows + bias (consumed only after the post-load barrier)
    if (tid < TM) rows_s[tid] = (tid < nrows) ? g_rowOrder[base + tid] : -1;
    if (tid >= 128) bias_s[tid - 128] = Bias[e * FF + (tid - 128)];

    // --- B: cp.async fp16 W (32KB), 128 k-rows x 16 chunks of 16B
    {
        const char* WB = (const char*)(g_Wh + (size_t)e * DD * FF);
        #pragma unroll
        for (int it = 0; it < 8; it++) {
            int idx = tid + it * 256;          // 2048
            int k     = idx >> 4;
            int chunk = idx & 15;
            CP_ASYNC16(sbase + SM_B + (uint32_t)(k * AROWB + chunk * 16),
                       WB + (uint32_t)(k * 256 + chunk * 16));
        }
    }

    // --- A: on-the-fly fp32 -> fp16 (32 rows x 32 float4); rowOrder read
    //     directly from gmem so no barrier is needed before the gather.
    #pragma unroll
    for (int it = 0; it < 4; it++) {
        int idx = tid + it * 256;              // 1024
        int m  = idx >> 5;
        int c4 = idx & 31;
        int r = (m < nrows) ? g_rowOrder[base + m] : -1;
        float4 v = (r >= 0) ? *(const float4*)&X[(size_t)r * DD + c4 * 4]
                            : make_float4(0.f, 0.f, 0.f, 0.f);
        __half2 h01 = __float22half2_rn(make_float2(v.x, v.y));
        __half2 h23 = __float22half2_rn(make_float2(v.z, v.w));
        uint2 hv = make_uint2(*(uint32_t*)&h01, *(uint32_t*)&h23);
        *(uint2*)(smem + SM_A + (uint32_t)(m * AROWB + c4 * 8)) = hv;
    }
    CP_COMMIT_WAIT();
    __syncthreads();

    // --- Warp tiling: 8 warps = 2(M) x 4(N); warp tile 16x32
    int warpM = wid >> 2;     // 0..1
    int warpN = wid & 3;      // 0..3

    float acc[4][4];
    #pragma unroll
    for (int nn = 0; nn < 4; nn++)
        #pragma unroll
        for (int q = 0; q < 4; q++) acc[nn][q] = 0.f;

    uint32_t aLane = sbase + SM_A
                   + (uint32_t)((warpM * 16 + (lid & 15)) * AROWB
                   + (lid >> 4) * 16);
    uint32_t bLane = sbase + SM_B
                   + (uint32_t)((lid & 15) * AROWB
                   + (warpN * 32 + (lid >> 4) * 8) * 2);

    #pragma unroll
    for (int k0 = 0; k0 < DD; k0 += 16) {
        uint32_t a0, a1, a2, a3;
        LDSM_X4(a0, a1, a2, a3, aLane + k0 * 2);
        uint32_t bfr[2][4];
        #pragma unroll
        for (int jn = 0; jn < 2; jn++)
            LDSM_X4_T(bfr[jn][0], bfr[jn][1], bfr[jn][2], bfr[jn][3],
                      bLane + k0 * AROWB + jn * 32);
        #pragma unroll
        for (int jn = 0; jn < 2; jn++) {
            MMA_16816_F16(acc[jn * 2],     a0, a1, a2, a3,
                          bfr[jn][0], bfr[jn][1]);
            MMA_16816_F16(acc[jn * 2 + 1], a0, a1, a2, a3,
                          bfr[jn][2], bfr[jn][3]);
        }
    }

    // --- Epilogue: c-frag layout -> gmem with bias
    int m0 = warpM * 16 + (lid >> 2);
    int m1 = m0 + 8;
    int gr0 = rows_s[m0];
    int gr1 = rows_s[m1];
    int colBase = warpN * 32 + (lid & 3) * 2;
    #pragma unroll
    for (int nn = 0; nn < 4; nn++) {
        int col = colBase + nn * 8;
        float bx = bias_s[col], by = bias_s[col + 1];
        if (gr0 >= 0) {
            float2 o = make_float2(acc[nn][0] + bx, acc[nn][1] + by);
            *(float2*)&Y[(size_t)gr0 * FF + col] = o;
        }
        if (gr1 >= 0) {
            float2 o = make_float2(acc[nn][2] + bx, acc[nn][3] + by);
            *(float2*)&Y[(size_t)gr1 * FF + col] = o;
        }
    }
}

// ---------------------------------------------------------------------------
extern "C" void kernel_launch(void* const* d_in, const int* in_sizes, int n_in,
                              void* d_out, int out_size) {
    const float* X    = (const float*)d_in[0];   // [B, D] fp32
    const int*   tidx = (const int*)d_in[1];     // [B] int32
    const float* W    = (const float*)d_in[2];   // [T, D, F] fp32
    const float* Bias = (const float*)d_in[3];   // [T, F] fp32
    float* Y = (float*)d_out;                    // [B, F] fp32

    (void)in_sizes; (void)n_in; (void)out_size;

    cudaFuncSetAttribute(k_gemm, cudaFuncAttributeMaxDynamicSharedMemorySize,
                         SM_TOTAL);

    k_prep<<<NBLK + CONVBLK, 256>>>(tidx, W);
    k_gemm<<<MAX_TILES, 256, SM_TOTAL>>>(X, Bias, Y);
}